// round 11
// baseline (speedup 1.0000x reference)
#include <cuda_runtime.h>
#include <cuda_bf16.h>
#include <cstdint>
#include <math.h>

// kv (16,1024,259) f32, positions (16,1024,3) f32, out (16,1024,3) f32
#define BATCH     16
#define NN        1024
#define EE        128
#define CC        259
#define TN        128          // n rows per block
#define TM        64           // m cols per tile
#define NT        (NN / TM)    // 16 tiles
#define NTHREADS  256
#define INV_SQRT_E 0.0883883476483184406f

// smem rows: 128 bf16 + 8 pad = 272 B (17 x 16B -> ldmatrix conflict-free)
#define ROWB      272
#define OFF_POS   0
#define POS_BYTES (NN * 3 * 4)               // 12288
#define OFF_KHI   (OFF_POS + POS_BYTES)      // 12288
#define KMAT      (TN * ROWB)                // 34816
#define OFF_KLO   (OFF_KHI + KMAT)           // 47104
#define OFF_V     (OFF_KLO + KMAT)           // 81920
#define VMAT      (TM * ROWB)                // 17408
#define VBUF      (2 * VMAT)                 // vhi + vlo = 34816
#define SMEM_TOTAL (OFF_V + 2 * VBUF)        // 151552 B

// ---------------- PTX helpers ----------------
__device__ __forceinline__ uint32_t smem_u32(const void* p) {
    uint32_t a;
    asm("{ .reg .u64 t; cvta.to.shared.u64 t, %1; cvt.u32.u64 %0, t; }" : "=r"(a) : "l"(p));
    return a;
}
__device__ __forceinline__ void ldsm4(uint32_t* r, uint32_t addr) {
    asm volatile("ldmatrix.sync.aligned.m8n8.x4.shared.b16 {%0,%1,%2,%3}, [%4];"
                 : "=r"(r[0]), "=r"(r[1]), "=r"(r[2]), "=r"(r[3]) : "r"(addr));
}
__device__ __forceinline__ void mma_bf16(float* d, const uint32_t* a, uint32_t b0, uint32_t b1) {
    asm volatile(
        "mma.sync.aligned.m16n8k16.row.col.f32.bf16.bf16.f32 "
        "{%0,%1,%2,%3}, {%4,%5,%6,%7}, {%8,%9}, {%0,%1,%2,%3};"
        : "+f"(d[0]), "+f"(d[1]), "+f"(d[2]), "+f"(d[3])
        : "r"(a[0]), "r"(a[1]), "r"(a[2]), "r"(a[3]), "r"(b0), "r"(b1));
}
// split x into bf16 hi + bf16 lo (lo = bf16(x - float(hi)))
__device__ __forceinline__ void split2(float x0, float x1, uint32_t& hi, uint32_t& lo) {
    __nv_bfloat16 h0 = __float2bfloat16(x0), h1 = __float2bfloat16(x1);
    __nv_bfloat16 l0 = __float2bfloat16(x0 - __bfloat162float(h0));
    __nv_bfloat16 l1 = __float2bfloat16(x1 - __bfloat162float(h1));
    hi = (uint32_t)__bfloat16_as_ushort(h0) | ((uint32_t)__bfloat16_as_ushort(h1) << 16);
    lo = (uint32_t)__bfloat16_as_ushort(l0) | ((uint32_t)__bfloat16_as_ushort(l1) << 16);
}

__global__ __launch_bounds__(NTHREADS, 1)
void actor_mma_kernel(const float* __restrict__ kv,
                      const float* __restrict__ pos,
                      float* __restrict__ out)
{
    extern __shared__ char smem[];
    const uint32_t sb = smem_u32(smem);
    float* pos_s = (float*)(smem + OFF_POS);

    const int tid  = threadIdx.x;
    const int w    = tid >> 5;
    const int lane = tid & 31;
    const int b    = blockIdx.y;
    const int n0   = blockIdx.x * TN;

    const float* kvb  = kv  + (size_t)b * NN * CC;
    const float* posb = pos + (size_t)b * NN * 3;

    // ---- stage all m positions ----
    for (int i = tid; i < NN * 3; i += NTHREADS) pos_s[i] = posb[i];

    // ---- stage K (prescaled), split hi/lo ----
    for (int q = tid; q < TN * 32; q += NTHREADS) {      // 32 float4-groups/row
        int r = q >> 5, c4 = q & 31;
        const float* src = kvb + (size_t)(n0 + r) * CC + c4 * 4;
        float x0 = src[0] * INV_SQRT_E, x1 = src[1] * INV_SQRT_E;
        float x2 = src[2] * INV_SQRT_E, x3 = src[3] * INV_SQRT_E;
        uint32_t h01, l01, h23, l23;
        split2(x0, x1, h01, l01);
        split2(x2, x3, h23, l23);
        uint32_t off = (uint32_t)r * ROWB + (uint32_t)c4 * 8;
        *(uint2*)(smem + OFF_KHI + off) = make_uint2(h01, h23);
        *(uint2*)(smem + OFF_KLO + off) = make_uint2(l01, l23);
    }

    // ---- stage V tile 0 ----
    for (int q = tid; q < TM * 32; q += NTHREADS) {
        int r = q >> 5, c4 = q & 31;
        const float* src = kvb + (size_t)r * CC + EE + c4 * 4;
        uint32_t h01, l01, h23, l23;
        split2(src[0], src[1], h01, l01);
        split2(src[2], src[3], h23, l23);
        uint32_t off = (uint32_t)r * ROWB + (uint32_t)c4 * 8;
        *(uint2*)(smem + OFF_V + off)        = make_uint2(h01, h23);
        *(uint2*)(smem + OFF_V + VMAT + off) = make_uint2(l01, l23);
    }
    __syncthreads();

    // ---- per-thread n-row state (2 rows) ----
    const int r0loc = w * 16 + (lane >> 2);       // local n row; second = +8
    const float pn0x = posb[(size_t)(n0 + r0loc) * 3 + 0];
    const float pn0y = posb[(size_t)(n0 + r0loc) * 3 + 1];
    const float pn0z = posb[(size_t)(n0 + r0loc) * 3 + 2];
    const float pn1x = posb[(size_t)(n0 + r0loc + 8) * 3 + 0];
    const float pn1y = posb[(size_t)(n0 + r0loc + 8) * 3 + 1];
    const float pn1z = posb[(size_t)(n0 + r0loc + 8) * 3 + 2];
    float a0x = 0.f, a0y = 0.f, a0z = 0.f, a1x = 0.f, a1y = 0.f, a1z = 0.f;

    // ldmatrix lane address components
    const uint32_t a_row  = (uint32_t)(w * 16 + (lane & 15));
    const uint32_t a_coff = (uint32_t)(lane >> 4) * 16;
    const uint32_t b_row  = (uint32_t)((lane & 7) + ((lane >> 4) & 1) * 8);
    const uint32_t b_coff = (uint32_t)((lane >> 3) & 1) * 16;
    const uint32_t a_hi_base = sb + OFF_KHI + a_row * ROWB + a_coff;
    const uint32_t a_lo_base = sb + OFF_KLO + a_row * ROWB + a_coff;

    for (int t = 0; t < NT; t++) {
        // prefetch next V tile into registers (scalar: CC=259 kills alignment)
        float vreg[32];
        if (t + 1 < NT) {
            const float* vsrc = kvb + (size_t)(t + 1) * TM * CC + EE;
            #pragma unroll
            for (int i = 0; i < 8; i++) {
                int q = i * NTHREADS + tid;        // 0..2047
                int r = q >> 5, c4 = q & 31;
                const float* s = vsrc + (size_t)r * CC + c4 * 4;
                vreg[i * 4 + 0] = s[0]; vreg[i * 4 + 1] = s[1];
                vreg[i * 4 + 2] = s[2]; vreg[i * 4 + 3] = s[3];
            }
        }

        const uint32_t vb    = sb + OFF_V + (uint32_t)(t & 1) * VBUF;
        const uint32_t b_hi0 = vb + b_row * ROWB + b_coff;
        const uint32_t b_lo0 = b_hi0 + VMAT;

        float acc[8][4];
        #pragma unroll
        for (int i = 0; i < 8; i++)
            #pragma unroll
            for (int j = 0; j < 4; j++) acc[i][j] = 0.f;

        #pragma unroll
        for (int k = 0; k < 8; k++) {             // e chunks of 16
            uint32_t ahi[4], alo[4];
            ldsm4(ahi, a_hi_base + (uint32_t)k * 32);
            ldsm4(alo, a_lo_base + (uint32_t)k * 32);
            // hoist ALL B fragments for this k-chunk (8 ldsm4, 32 regs)
            uint32_t bhi[4][4], blo[4][4];
            #pragma unroll
            for (int p = 0; p < 4; p++) {
                uint32_t boff = (uint32_t)p * 16 * ROWB + (uint32_t)k * 32;
                ldsm4(bhi[p], b_hi0 + boff);
                ldsm4(blo[p], b_lo0 + boff);
            }
            // three passes over all 8 accumulators: reuse distance = 8 MMAs
            #pragma unroll
            for (int p = 0; p < 4; p++) {         // pass 1: hi*hi
                mma_bf16(acc[2*p],     ahi, bhi[p][0], bhi[p][1]);
                mma_bf16(acc[2*p + 1], ahi, bhi[p][2], bhi[p][3]);
            }
            #pragma unroll
            for (int p = 0; p < 4; p++) {         // pass 2: hi*lo
                mma_bf16(acc[2*p],     ahi, blo[p][0], blo[p][1]);
                mma_bf16(acc[2*p + 1], ahi, blo[p][2], blo[p][3]);
            }
            #pragma unroll
            for (int p = 0; p < 4; p++) {         // pass 3: lo*hi
                mma_bf16(acc[2*p],     alo, bhi[p][0], bhi[p][1]);
                mma_bf16(acc[2*p + 1], alo, bhi[p][2], bhi[p][3]);
            }
        }

        // store prefetched V into the other buffer
        if (t + 1 < NT) {
            char* dst = smem + OFF_V + ((t + 1) & 1) * VBUF;
            #pragma unroll
            for (int i = 0; i < 8; i++) {
                int q = i * NTHREADS + tid;
                int r = q >> 5, c4 = q & 31;
                uint32_t h01, l01, h23, l23;
                split2(vreg[i*4+0], vreg[i*4+1], h01, l01);
                split2(vreg[i*4+2], vreg[i*4+3], h23, l23);
                uint32_t off = (uint32_t)r * ROWB + (uint32_t)c4 * 8;
                *(uint2*)(dst + off)        = make_uint2(h01, h23);
                *(uint2*)(dst + VMAT + off) = make_uint2(l01, l23);
            }
        }

        // ---- fused epilogue on this tile's S fragments ----
        const int mbase = t * TM;
        #pragma unroll
        for (int bi = 0; bi < 8; bi++) {
            #pragma unroll
            for (int cc = 0; cc < 2; cc++) {
                int ml = bi * 8 + (lane & 3) * 2 + cc;
                const float* pm = pos_s + (mbase + ml) * 3;
                float pmx = pm[0], pmy = pm[1], pmz = pm[2];
                // row r0loc
                {
                    float dx = pn0x - pmx, dy = pn0y - pmy, dz = pn0z - pmz;
                    float sq = fmaf(dx, dx, fmaf(dy, dy, fmaf(dz, dz, 1e-30f)));
                    float wg = acc[bi][cc] * rsqrtf(sq);     // diagonal: 0*finite=0
                    a0x = fmaf(dx, wg, a0x); a0y = fmaf(dy, wg, a0y); a0z = fmaf(dz, wg, a0z);
                }
                // row r0loc + 8
                {
                    float dx = pn1x - pmx, dy = pn1y - pmy, dz = pn1z - pmz;
                    float sq = fmaf(dx, dx, fmaf(dy, dy, fmaf(dz, dz, 1e-30f)));
                    float wg = acc[bi][2 + cc] * rsqrtf(sq);
                    a1x = fmaf(dx, wg, a1x); a1y = fmaf(dy, wg, a1y); a1z = fmaf(dz, wg, a1z);
                }
            }
        }
        __syncthreads();
    }

    // ---- reduce across the 4 lanes of each quad (same rows, different m-cols) ----
    #pragma unroll
    for (int off = 1; off <= 2; off <<= 1) {
        a0x += __shfl_xor_sync(0xffffffffu, a0x, off);
        a0y += __shfl_xor_sync(0xffffffffu, a0y, off);
        a0z += __shfl_xor_sync(0xffffffffu, a0z, off);
        a1x += __shfl_xor_sync(0xffffffffu, a1x, off);
        a1y += __shfl_xor_sync(0xffffffffu, a1y, off);
        a1z += __shfl_xor_sync(0xffffffffu, a1z, off);
    }
    if ((lane & 3) == 0) {
        float* o0 = out + ((size_t)b * NN + n0 + r0loc) * 3;
        o0[0] = 0.01f * tanhf(a0x);
        o0[1] = 0.01f * tanhf(a0y);
        o0[2] = 0.01f * tanhf(a0z);
        float* o1 = out + ((size_t)b * NN + n0 + r0loc + 8) * 3;
        o1[0] = 0.01f * tanhf(a1x);
        o1[1] = 0.01f * tanhf(a1y);
        o1[2] = 0.01f * tanhf(a1z);
    }
}

extern "C" void kernel_launch(void* const* d_in, const int* in_sizes, int n_in,
                              void* d_out, int out_size)
{
    const float* kv  = (const float*)d_in[0];
    const float* pos = (const float*)d_in[1];
    float* out = (float*)d_out;
    (void)in_sizes; (void)n_in; (void)out_size;

    cudaFuncSetAttribute(actor_mma_kernel,
                         cudaFuncAttributeMaxDynamicSharedMemorySize, SMEM_TOTAL);

    dim3 grid(NN / TN, BATCH);   // (8,16) = 128 blocks
    actor_mma_kernel<<<grid, NTHREADS, SMEM_TOTAL>>>(kv, pos, out);
}

// round 12
// speedup vs baseline: 1.0290x; 1.0290x over previous
#include <cuda_runtime.h>
#include <cuda_bf16.h>
#include <cstdint>
#include <math.h>

// kv (16,1024,259) f32, positions (16,1024,3) f32, out (16,1024,3) f32
#define BATCH     16
#define NN        1024
#define EE        128
#define CC        259
#define TN        128          // n rows per block
#define TM        64           // m cols per tile
#define NT        (NN / TM)    // 16 tiles
#define NTH       512          // 16 warps: 8 n-groups x 2 m-col halves
#define INV_SQRT_E 0.0883883476483184406f

// smem rows: 128 bf16 + 8 pad = 272 B (17 x 16B -> ldmatrix conflict-free)
#define ROWB      272
#define OFF_POS   0
#define POS_BYTES (NN * 3 * 4)               // 12288
#define OFF_KHI   (OFF_POS + POS_BYTES)      // 12288
#define KMAT      (TN * ROWB)                // 34816
#define OFF_KLO   (OFF_KHI + KMAT)           // 47104
#define OFF_V     (OFF_KLO + KMAT)           // 81920
#define VMAT      (TM * ROWB)                // 17408
#define VBUF      (2 * VMAT)                 // vhi + vlo = 34816
#define SMEM_TOTAL (OFF_V + 2 * VBUF)        // 151552 B

// ---------------- PTX helpers ----------------
__device__ __forceinline__ uint32_t smem_u32(const void* p) {
    uint32_t a;
    asm("{ .reg .u64 t; cvta.to.shared.u64 t, %1; cvt.u32.u64 %0, t; }" : "=r"(a) : "l"(p));
    return a;
}
__device__ __forceinline__ void ldsm4(uint32_t* r, uint32_t addr) {
    asm volatile("ldmatrix.sync.aligned.m8n8.x4.shared.b16 {%0,%1,%2,%3}, [%4];"
                 : "=r"(r[0]), "=r"(r[1]), "=r"(r[2]), "=r"(r[3]) : "r"(addr));
}
__device__ __forceinline__ void mma_bf16(float* d, const uint32_t* a, uint32_t b0, uint32_t b1) {
    asm volatile(
        "mma.sync.aligned.m16n8k16.row.col.f32.bf16.bf16.f32 "
        "{%0,%1,%2,%3}, {%4,%5,%6,%7}, {%8,%9}, {%0,%1,%2,%3};"
        : "+f"(d[0]), "+f"(d[1]), "+f"(d[2]), "+f"(d[3])
        : "r"(a[0]), "r"(a[1]), "r"(a[2]), "r"(a[3]), "r"(b0), "r"(b1));
}
// split x into bf16 hi + bf16 lo (lo = bf16(x - float(hi)))
__device__ __forceinline__ void split2(float x0, float x1, uint32_t& hi, uint32_t& lo) {
    __nv_bfloat16 h0 = __float2bfloat16(x0), h1 = __float2bfloat16(x1);
    __nv_bfloat16 l0 = __float2bfloat16(x0 - __bfloat162float(h0));
    __nv_bfloat16 l1 = __float2bfloat16(x1 - __bfloat162float(h1));
    hi = (uint32_t)__bfloat16_as_ushort(h0) | ((uint32_t)__bfloat16_as_ushort(h1) << 16);
    lo = (uint32_t)__bfloat16_as_ushort(l0) | ((uint32_t)__bfloat16_as_ushort(l1) << 16);
}

__global__ __launch_bounds__(NTH, 1)
void actor_mma_kernel(const float* __restrict__ kv,
                      const float* __restrict__ pos,
                      float* __restrict__ out)
{
    extern __shared__ char smem[];
    const uint32_t sb = smem_u32(smem);
    float* pos_s = (float*)(smem + OFF_POS);

    const int tid  = threadIdx.x;
    const int w    = tid >> 5;
    const int lane = tid & 31;
    const int wn   = w & 7;            // n-row group: rows wn*16 .. wn*16+15
    const int wm   = w >> 3;           // m-col half: cols wm*32 .. wm*32+31 of each tile
    const int b    = blockIdx.y;
    const int n0   = blockIdx.x * TN;

    const float* kvb  = kv  + (size_t)b * NN * CC;
    const float* posb = pos + (size_t)b * NN * 3;

    // ---- stage all m positions ----
    for (int i = tid; i < NN * 3; i += NTH) pos_s[i] = posb[i];

    // ---- stage K (prescaled), split hi/lo ----
    for (int q = tid; q < TN * 32; q += NTH) {           // 32 float4-groups/row
        int r = q >> 5, c4 = q & 31;
        const float* src = kvb + (size_t)(n0 + r) * CC + c4 * 4;
        float x0 = src[0] * INV_SQRT_E, x1 = src[1] * INV_SQRT_E;
        float x2 = src[2] * INV_SQRT_E, x3 = src[3] * INV_SQRT_E;
        uint32_t h01, l01, h23, l23;
        split2(x0, x1, h01, l01);
        split2(x2, x3, h23, l23);
        uint32_t off = (uint32_t)r * ROWB + (uint32_t)c4 * 8;
        *(uint2*)(smem + OFF_KHI + off) = make_uint2(h01, h23);
        *(uint2*)(smem + OFF_KLO + off) = make_uint2(l01, l23);
    }

    // ---- stage V tile 0 ----
    for (int q = tid; q < TM * 32; q += NTH) {
        int r = q >> 5, c4 = q & 31;
        const float* src = kvb + (size_t)r * CC + EE + c4 * 4;
        uint32_t h01, l01, h23, l23;
        split2(src[0], src[1], h01, l01);
        split2(src[2], src[3], h23, l23);
        uint32_t off = (uint32_t)r * ROWB + (uint32_t)c4 * 8;
        *(uint2*)(smem + OFF_V + off)        = make_uint2(h01, h23);
        *(uint2*)(smem + OFF_V + VMAT + off) = make_uint2(l01, l23);
    }
    __syncthreads();

    // ---- per-thread n-row state (2 rows) ----
    const int r0loc = wn * 16 + (lane >> 2);      // local n row; second = +8
    const float pn0x = posb[(size_t)(n0 + r0loc) * 3 + 0];
    const float pn0y = posb[(size_t)(n0 + r0loc) * 3 + 1];
    const float pn0z = posb[(size_t)(n0 + r0loc) * 3 + 2];
    const float pn1x = posb[(size_t)(n0 + r0loc + 8) * 3 + 0];
    const float pn1y = posb[(size_t)(n0 + r0loc + 8) * 3 + 1];
    const float pn1z = posb[(size_t)(n0 + r0loc + 8) * 3 + 2];
    float a0x = 0.f, a0y = 0.f, a0z = 0.f, a1x = 0.f, a1y = 0.f, a1z = 0.f;

    // ldmatrix lane address components
    const uint32_t a_row  = (uint32_t)(wn * 16 + (lane & 15));
    const uint32_t a_coff = (uint32_t)(lane >> 4) * 16;
    const uint32_t b_row  = (uint32_t)((lane & 7) + ((lane >> 4) & 1) * 8);
    const uint32_t b_coff = (uint32_t)((lane >> 3) & 1) * 16;
    const uint32_t a_hi_base = sb + OFF_KHI + a_row * ROWB + a_coff;
    const uint32_t a_lo_base = sb + OFF_KLO + a_row * ROWB + a_coff;

    for (int t = 0; t < NT; t++) {
        // prefetch next V tile into registers (scalar: CC=259 kills alignment)
        float vreg[16];
        if (t + 1 < NT) {
            const float* vsrc = kvb + (size_t)(t + 1) * TM * CC + EE;
            #pragma unroll
            for (int i = 0; i < 4; i++) {
                int q = i * NTH + tid;             // 0..2047
                int r = q >> 5, c4 = q & 31;
                const float* s = vsrc + (size_t)r * CC + c4 * 4;
                vreg[i * 4 + 0] = s[0]; vreg[i * 4 + 1] = s[1];
                vreg[i * 4 + 2] = s[2]; vreg[i * 4 + 3] = s[3];
            }
        }

        const uint32_t vb    = sb + OFF_V + (uint32_t)(t & 1) * VBUF;
        const uint32_t b_hi0 = vb + b_row * ROWB + b_coff;
        const uint32_t b_lo0 = b_hi0 + VMAT;

        float acc[4][4];                           // 2 m-octets (this half) x 2 row-groups
        #pragma unroll
        for (int i = 0; i < 4; i++)
            #pragma unroll
            for (int j = 0; j < 4; j++) acc[i][j] = 0.f;

        #pragma unroll
        for (int k = 0; k < 8; k++) {              // e chunks of 16
            uint32_t ahi[4], alo[4];
            ldsm4(ahi, a_hi_base + (uint32_t)k * 32);
            ldsm4(alo, a_lo_base + (uint32_t)k * 32);
            uint32_t bhi[2][4], blo[2][4];
            #pragma unroll
            for (int p = 0; p < 2; p++) {          // this warp's two 16-col groups
                uint32_t boff = (uint32_t)(wm * 2 + p) * 16 * ROWB + (uint32_t)k * 32;
                ldsm4(bhi[p], b_hi0 + boff);
                ldsm4(blo[p], b_lo0 + boff);
            }
            #pragma unroll
            for (int p = 0; p < 2; p++) {          // hi*hi
                mma_bf16(acc[2*p],     ahi, bhi[p][0], bhi[p][1]);
                mma_bf16(acc[2*p + 1], ahi, bhi[p][2], bhi[p][3]);
            }
            #pragma unroll
            for (int p = 0; p < 2; p++) {          // hi*lo
                mma_bf16(acc[2*p],     ahi, blo[p][0], blo[p][1]);
                mma_bf16(acc[2*p + 1], ahi, blo[p][2], blo[p][3]);
            }
            #pragma unroll
            for (int p = 0; p < 2; p++) {          // lo*hi
                mma_bf16(acc[2*p],     alo, bhi[p][0], bhi[p][1]);
                mma_bf16(acc[2*p + 1], alo, bhi[p][2], bhi[p][3]);
            }
        }

        // store prefetched V into the other buffer
        if (t + 1 < NT) {
            char* dst = smem + OFF_V + ((t + 1) & 1) * VBUF;
            #pragma unroll
            for (int i = 0; i < 4; i++) {
                int q = i * NTH + tid;
                int r = q >> 5, c4 = q & 31;
                uint32_t h01, l01, h23, l23;
                split2(vreg[i*4+0], vreg[i*4+1], h01, l01);
                split2(vreg[i*4+2], vreg[i*4+3], h23, l23);
                uint32_t off = (uint32_t)r * ROWB + (uint32_t)c4 * 8;
                *(uint2*)(dst + off)        = make_uint2(h01, h23);
                *(uint2*)(dst + VMAT + off) = make_uint2(l01, l23);
            }
        }

        // ---- fused epilogue on this warp's half of the tile ----
        const int mbase = t * TM + wm * 32;
        #pragma unroll
        for (int bi = 0; bi < 4; bi++) {
            #pragma unroll
            for (int cc = 0; cc < 2; cc++) {
                int ml = bi * 8 + (lane & 3) * 2 + cc;
                const float* pm = pos_s + (mbase + ml) * 3;
                float pmx = pm[0], pmy = pm[1], pmz = pm[2];
                {
                    float dx = pn0x - pmx, dy = pn0y - pmy, dz = pn0z - pmz;
                    float sq = fmaf(dx, dx, fmaf(dy, dy, fmaf(dz, dz, 1e-30f)));
                    float wg = acc[bi][cc] * rsqrtf(sq);     // diagonal: 0*finite=0
                    a0x = fmaf(dx, wg, a0x); a0y = fmaf(dy, wg, a0y); a0z = fmaf(dz, wg, a0z);
                }
                {
                    float dx = pn1x - pmx, dy = pn1y - pmy, dz = pn1z - pmz;
                    float sq = fmaf(dx, dx, fmaf(dy, dy, fmaf(dz, dz, 1e-30f)));
                    float wg = acc[bi][2 + cc] * rsqrtf(sq);
                    a1x = fmaf(dx, wg, a1x); a1y = fmaf(dy, wg, a1y); a1z = fmaf(dz, wg, a1z);
                }
            }
        }
        __syncthreads();
    }

    // ---- reduce across the 4 lanes of each quad (same rows, different m-cols) ----
    #pragma unroll
    for (int off = 1; off <= 2; off <<= 1) {
        a0x += __shfl_xor_sync(0xffffffffu, a0x, off);
        a0y += __shfl_xor_sync(0xffffffffu, a0y, off);
        a0z += __shfl_xor_sync(0xffffffffu, a0z, off);
        a1x += __shfl_xor_sync(0xffffffffu, a1x, off);
        a1y += __shfl_xor_sync(0xffffffffu, a1y, off);
        a1z += __shfl_xor_sync(0xffffffffu, a1z, off);
    }

    // ---- combine the two m-col halves (warps w and w+8) via smem scratch ----
    float* scratch = (float*)(smem + OFF_V);      // V buffers dead now
    if (wm == 1 && (lane & 3) == 0) {
        scratch[r0loc * 3 + 0] = a0x;
        scratch[r0loc * 3 + 1] = a0y;
        scratch[r0loc * 3 + 2] = a0z;
        scratch[(r0loc + 8) * 3 + 0] = a1x;
        scratch[(r0loc + 8) * 3 + 1] = a1y;
        scratch[(r0loc + 8) * 3 + 2] = a1z;
    }
    __syncthreads();
    if (wm == 0 && (lane & 3) == 0) {
        float ax0 = a0x + scratch[r0loc * 3 + 0];
        float ay0 = a0y + scratch[r0loc * 3 + 1];
        float az0 = a0z + scratch[r0loc * 3 + 2];
        float ax1 = a1x + scratch[(r0loc + 8) * 3 + 0];
        float ay1 = a1y + scratch[(r0loc + 8) * 3 + 1];
        float az1 = a1z + scratch[(r0loc + 8) * 3 + 2];
        float* o0 = out + ((size_t)b * NN + n0 + r0loc) * 3;
        o0[0] = 0.01f * tanhf(ax0);
        o0[1] = 0.01f * tanhf(ay0);
        o0[2] = 0.01f * tanhf(az0);
        float* o1 = out + ((size_t)b * NN + n0 + r0loc + 8) * 3;
        o1[0] = 0.01f * tanhf(ax1);
        o1[1] = 0.01f * tanhf(ay1);
        o1[2] = 0.01f * tanhf(az1);
    }
}

extern "C" void kernel_launch(void* const* d_in, const int* in_sizes, int n_in,
                              void* d_out, int out_size)
{
    const float* kv  = (const float*)d_in[0];
    const float* pos = (const float*)d_in[1];
    float* out = (float*)d_out;
    (void)in_sizes; (void)n_in; (void)out_size;

    cudaFuncSetAttribute(actor_mma_kernel,
                         cudaFuncAttributeMaxDynamicSharedMemorySize, SMEM_TOTAL);

    dim3 grid(NN / TN, BATCH);   // (8,16) = 128 blocks
    actor_mma_kernel<<<grid, NTH, SMEM_TOTAL>>>(kv, pos, out);
}

// round 13
// speedup vs baseline: 1.1583x; 1.1257x over previous
#include <cuda_runtime.h>
#include <cuda_bf16.h>
#include <cstdint>
#include <math.h>

// kv (16,1024,259) f32, positions (16,1024,3) f32, out (16,1024,3) f32
#define BATCH     16
#define NN        1024
#define EE        128
#define CC        259
#define TN        128          // n rows per block
#define TM        64           // m cols per tile
#define NT        (NN / TM)    // 16 tiles
#define NTH       512          // 16 warps: 8 n-groups x 2 m-col halves
#define INV_SQRT_E 0.0883883476483184406f

// smem rows: 128 bf16 + 8 pad = 272 B (17 x 16B -> ldmatrix conflict-free)
#define ROWB      272
#define OFF_POS   0
#define POS_BYTES (NN * 3 * 4)               // 12288
#define OFF_KHI   (OFF_POS + POS_BYTES)      // 12288
#define KMAT      (TN * ROWB)                // 34816
#define OFF_KLO   (OFF_KHI + KMAT)           // 47104
#define OFF_V     (OFF_KLO + KMAT)           // 81920
#define VMAT      (TM * ROWB)                // 17408
#define VBUF      (2 * VMAT)                 // vhi + vlo = 34816
#define SMEM_TOTAL (OFF_V + 2 * VBUF)        // 151552 B

// ---------------- PTX helpers ----------------
__device__ __forceinline__ uint32_t smem_u32(const void* p) {
    uint32_t a;
    asm("{ .reg .u64 t; cvta.to.shared.u64 t, %1; cvt.u32.u64 %0, t; }" : "=r"(a) : "l"(p));
    return a;
}
__device__ __forceinline__ void ldsm4(uint32_t* r, uint32_t addr) {
    asm volatile("ldmatrix.sync.aligned.m8n8.x4.shared.b16 {%0,%1,%2,%3}, [%4];"
                 : "=r"(r[0]), "=r"(r[1]), "=r"(r[2]), "=r"(r[3]) : "r"(addr));
}
__device__ __forceinline__ void mma_bf16(float* d, const uint32_t* a, uint32_t b0, uint32_t b1) {
    asm volatile(
        "mma.sync.aligned.m16n8k16.row.col.f32.bf16.bf16.f32 "
        "{%0,%1,%2,%3}, {%4,%5,%6,%7}, {%8,%9}, {%0,%1,%2,%3};"
        : "+f"(d[0]), "+f"(d[1]), "+f"(d[2]), "+f"(d[3])
        : "r"(a[0]), "r"(a[1]), "r"(a[2]), "r"(a[3]), "r"(b0), "r"(b1));
}
// split x into bf16 hi + bf16 lo (lo = bf16(x - float(hi)))
__device__ __forceinline__ void split2(float x0, float x1, uint32_t& hi, uint32_t& lo) {
    __nv_bfloat16 h0 = __float2bfloat16(x0), h1 = __float2bfloat16(x1);
    __nv_bfloat16 l0 = __float2bfloat16(x0 - __bfloat162float(h0));
    __nv_bfloat16 l1 = __float2bfloat16(x1 - __bfloat162float(h1));
    hi = (uint32_t)__bfloat16_as_ushort(h0) | ((uint32_t)__bfloat16_as_ushort(h1) << 16);
    lo = (uint32_t)__bfloat16_as_ushort(l0) | ((uint32_t)__bfloat16_as_ushort(l1) << 16);
}

__global__ __launch_bounds__(NTH, 1)
void actor_mma_kernel(const float* __restrict__ kv,
                      const float* __restrict__ pos,
                      float* __restrict__ out)
{
    extern __shared__ char smem[];
    const uint32_t sb = smem_u32(smem);
    float* pos_s = (float*)(smem + OFF_POS);

    const int tid  = threadIdx.x;
    const int w    = tid >> 5;
    const int lane = tid & 31;
    const int wn   = w & 7;            // n-row group: rows wn*16 .. wn*16+15
    const int wm   = w >> 3;           // m-col half: cols wm*32 .. wm*32+31 of each tile
    const int b    = blockIdx.y;
    const int n0   = blockIdx.x * TN;

    const float* kvb  = kv  + (size_t)b * NN * CC;
    const float* posb = pos + (size_t)b * NN * 3;

    // ---- stage all m positions ----
    for (int i = tid; i < NN * 3; i += NTH) pos_s[i] = posb[i];

    // ---- stage K (prescaled), split hi/lo ----
    for (int q = tid; q < TN * 32; q += NTH) {           // 32 float4-groups/row
        int r = q >> 5, c4 = q & 31;
        const float* src = kvb + (size_t)(n0 + r) * CC + c4 * 4;
        float x0 = src[0] * INV_SQRT_E, x1 = src[1] * INV_SQRT_E;
        float x2 = src[2] * INV_SQRT_E, x3 = src[3] * INV_SQRT_E;
        uint32_t h01, l01, h23, l23;
        split2(x0, x1, h01, l01);
        split2(x2, x3, h23, l23);
        uint32_t off = (uint32_t)r * ROWB + (uint32_t)c4 * 8;
        *(uint2*)(smem + OFF_KHI + off) = make_uint2(h01, h23);
        *(uint2*)(smem + OFF_KLO + off) = make_uint2(l01, l23);
    }

    // ---- stage V tile 0 ----
    for (int q = tid; q < TM * 32; q += NTH) {
        int r = q >> 5, c4 = q & 31;
        const float* src = kvb + (size_t)r * CC + EE + c4 * 4;
        uint32_t h01, l01, h23, l23;
        split2(src[0], src[1], h01, l01);
        split2(src[2], src[3], h23, l23);
        uint32_t off = (uint32_t)r * ROWB + (uint32_t)c4 * 8;
        *(uint2*)(smem + OFF_V + off)        = make_uint2(h01, h23);
        *(uint2*)(smem + OFF_V + VMAT + off) = make_uint2(l01, l23);
    }
    __syncthreads();

    // ---- per-thread n-row state (2 rows) ----
    const int r0loc = wn * 16 + (lane >> 2);      // local n row; second = +8
    const float pn0x = posb[(size_t)(n0 + r0loc) * 3 + 0];
    const float pn0y = posb[(size_t)(n0 + r0loc) * 3 + 1];
    const float pn0z = posb[(size_t)(n0 + r0loc) * 3 + 2];
    const float pn1x = posb[(size_t)(n0 + r0loc + 8) * 3 + 0];
    const float pn1y = posb[(size_t)(n0 + r0loc + 8) * 3 + 1];
    const float pn1z = posb[(size_t)(n0 + r0loc + 8) * 3 + 2];
    float a0x = 0.f, a0y = 0.f, a0z = 0.f, a1x = 0.f, a1y = 0.f, a1z = 0.f;

    // ldmatrix lane address components
    const uint32_t a_row  = (uint32_t)(wn * 16 + (lane & 15));
    const uint32_t a_coff = (uint32_t)(lane >> 4) * 16;
    const uint32_t b_row  = (uint32_t)((lane & 7) + ((lane >> 4) & 1) * 8);
    const uint32_t b_coff = (uint32_t)((lane >> 3) & 1) * 16;
    const uint32_t a_hi_base = sb + OFF_KHI + a_row * ROWB + a_coff;
    const uint32_t a_lo_base = sb + OFF_KLO + a_row * ROWB + a_coff;

    float accA[4][4], accB[4][4];

    // ---- pipeline stage lambdas (all fully inlined) ----
    auto prefetch_v = [&](int t1, float (&vreg)[16]) {
        if (t1 < NT) {
            const float* vsrc = kvb + (size_t)t1 * TM * CC + EE;
            #pragma unroll
            for (int i = 0; i < 4; i++) {
                int q = i * NTH + tid;             // 0..2047
                int r = q >> 5, c4 = q & 31;
                const float* s = vsrc + (size_t)r * CC + c4 * 4;
                vreg[i * 4 + 0] = s[0]; vreg[i * 4 + 1] = s[1];
                vreg[i * 4 + 2] = s[2]; vreg[i * 4 + 3] = s[3];
            }
        }
    };
    auto store_v = [&](int t1, float (&vreg)[16]) {
        if (t1 < NT) {
            char* dst = smem + OFF_V + (t1 & 1) * VBUF;
            #pragma unroll
            for (int i = 0; i < 4; i++) {
                int q = i * NTH + tid;
                int r = q >> 5, c4 = q & 31;
                uint32_t h01, l01, h23, l23;
                split2(vreg[i*4+0], vreg[i*4+1], h01, l01);
                split2(vreg[i*4+2], vreg[i*4+3], h23, l23);
                uint32_t off = (uint32_t)r * ROWB + (uint32_t)c4 * 8;
                *(uint2*)(dst + off)        = make_uint2(h01, h23);
                *(uint2*)(dst + VMAT + off) = make_uint2(l01, l23);
            }
        }
    };
    auto mma_tile = [&](int t, float (&acc)[4][4]) {
        const uint32_t vb    = sb + OFF_V + (uint32_t)(t & 1) * VBUF;
        const uint32_t b_hi0 = vb + b_row * ROWB + b_coff;
        const uint32_t b_lo0 = b_hi0 + VMAT;
        #pragma unroll
        for (int i = 0; i < 4; i++)
            #pragma unroll
            for (int j = 0; j < 4; j++) acc[i][j] = 0.f;
        #pragma unroll
        for (int k = 0; k < 8; k++) {              // e chunks of 16
            uint32_t ahi[4], alo[4];
            ldsm4(ahi, a_hi_base + (uint32_t)k * 32);
            ldsm4(alo, a_lo_base + (uint32_t)k * 32);
            uint32_t bhi[2][4], blo[2][4];
            #pragma unroll
            for (int p = 0; p < 2; p++) {          // this warp's two 16-col groups
                uint32_t boff = (uint32_t)(wm * 2 + p) * 16 * ROWB + (uint32_t)k * 32;
                ldsm4(bhi[p], b_hi0 + boff);
                ldsm4(blo[p], b_lo0 + boff);
            }
            #pragma unroll
            for (int p = 0; p < 2; p++) {          // hi*hi
                mma_bf16(acc[2*p],     ahi, bhi[p][0], bhi[p][1]);
                mma_bf16(acc[2*p + 1], ahi, bhi[p][2], bhi[p][3]);
            }
            #pragma unroll
            for (int p = 0; p < 2; p++) {          // hi*lo
                mma_bf16(acc[2*p],     ahi, blo[p][0], blo[p][1]);
                mma_bf16(acc[2*p + 1], ahi, blo[p][2], blo[p][3]);
            }
            #pragma unroll
            for (int p = 0; p < 2; p++) {          // lo*hi
                mma_bf16(acc[2*p],     alo, bhi[p][0], bhi[p][1]);
                mma_bf16(acc[2*p + 1], alo, bhi[p][2], bhi[p][3]);
            }
        }
    };
    auto epi = [&](int t, float (&acc)[4][4]) {
        const int mbase = t * TM + wm * 32;
        #pragma unroll
        for (int bi = 0; bi < 4; bi++) {
            #pragma unroll
            for (int cc = 0; cc < 2; cc++) {
                int ml = bi * 8 + (lane & 3) * 2 + cc;
                const float* pm = pos_s + (mbase + ml) * 3;
                float pmx = pm[0], pmy = pm[1], pmz = pm[2];
                {
                    float dx = pn0x - pmx, dy = pn0y - pmy, dz = pn0z - pmz;
                    float sq = fmaf(dx, dx, fmaf(dy, dy, fmaf(dz, dz, 1e-30f)));
                    float wg = acc[bi][cc] * rsqrtf(sq);     // diagonal: 0*finite=0
                    a0x = fmaf(dx, wg, a0x); a0y = fmaf(dy, wg, a0y); a0z = fmaf(dz, wg, a0z);
                }
                {
                    float dx = pn1x - pmx, dy = pn1y - pmy, dz = pn1z - pmz;
                    float sq = fmaf(dx, dx, fmaf(dy, dy, fmaf(dz, dz, 1e-30f)));
                    float wg = acc[bi][2 + cc] * rsqrtf(sq);
                    a1x = fmaf(dx, wg, a1x); a1y = fmaf(dy, wg, a1y); a1z = fmaf(dz, wg, a1z);
                }
            }
        }
    };

    // ---- software-pipelined main loop: epilogue lags MMA by one tile ----
    {   // t = 0: fill stage, no epilogue yet
        float vreg[16];
        prefetch_v(1, vreg);
        mma_tile(0, accA);
        store_v(1, vreg);
        __syncthreads();
    }
    #pragma unroll 1
    for (int t = 1; t <= NT - 3; t += 2) {
        {   // odd t: MMA -> accB, epilogue(t-1) on accA
            float vreg[16];
            prefetch_v(t + 1, vreg);
            mma_tile(t, accB);
            store_v(t + 1, vreg);
            epi(t - 1, accA);
            __syncthreads();
        }
        {   // even t+1: MMA -> accA, epilogue(t) on accB
            float vreg[16];
            prefetch_v(t + 2, vreg);
            mma_tile(t + 1, accA);
            store_v(t + 2, vreg);
            epi(t, accB);
            __syncthreads();
        }
    }
    {   // t = NT-1 (odd): last MMA -> accB, epilogue(NT-2) on accA
        mma_tile(NT - 1, accB);
        epi(NT - 2, accA);
        __syncthreads();
    }
    epi(NT - 1, accB);   // drain

    // ---- reduce across the 4 lanes of each quad (same rows, different m-cols) ----
    #pragma unroll
    for (int off = 1; off <= 2; off <<= 1) {
        a0x += __shfl_xor_sync(0xffffffffu, a0x, off);
        a0y += __shfl_xor_sync(0xffffffffu, a0y, off);
        a0z += __shfl_xor_sync(0xffffffffu, a0z, off);
        a1x += __shfl_xor_sync(0xffffffffu, a1x, off);
        a1y += __shfl_xor_sync(0xffffffffu, a1y, off);
        a1z += __shfl_xor_sync(0xffffffffu, a1z, off);
    }

    __syncthreads();   // all V reads done before scratch reuse
    // ---- combine the two m-col halves (warps w and w+8) via smem scratch ----
    float* scratch = (float*)(smem + OFF_V);      // V buffers dead now
    if (wm == 1 && (lane & 3) == 0) {
        scratch[r0loc * 3 + 0] = a0x;
        scratch[r0loc * 3 + 1] = a0y;
        scratch[r0loc * 3 + 2] = a0z;
        scratch[(r0loc + 8) * 3 + 0] = a1x;
        scratch[(r0loc + 8) * 3 + 1] = a1y;
        scratch[(r0loc + 8) * 3 + 2] = a1z;
    }
    __syncthreads();
    if (wm == 0 && (lane & 3) == 0) {
        float ax0 = a0x + scratch[r0loc * 3 + 0];
        float ay0 = a0y + scratch[r0loc * 3 + 1];
        float az0 = a0z + scratch[r0loc * 3 + 2];
        float ax1 = a1x + scratch[(r0loc + 8) * 3 + 0];
        float ay1 = a1y + scratch[(r0loc + 8) * 3 + 1];
        float az1 = a1z + scratch[(r0loc + 8) * 3 + 2];
        float* o0 = out + ((size_t)b * NN + n0 + r0loc) * 3;
        o0[0] = 0.01f * tanhf(ax0);
        o0[1] = 0.01f * tanhf(ay0);
        o0[2] = 0.01f * tanhf(az0);
        float* o1 = out + ((size_t)b * NN + n0 + r0loc + 8) * 3;
        o1[0] = 0.01f * tanhf(ax1);
        o1[1] = 0.01f * tanhf(ay1);
        o1[2] = 0.01f * tanhf(az1);
    }
}

extern "C" void kernel_launch(void* const* d_in, const int* in_sizes, int n_in,
                              void* d_out, int out_size)
{
    const float* kv  = (const float*)d_in[0];
    const float* pos = (const float*)d_in[1];
    float* out = (float*)d_out;
    (void)in_sizes; (void)n_in; (void)out_size;

    cudaFuncSetAttribute(actor_mma_kernel,
                         cudaFuncAttributeMaxDynamicSharedMemorySize, SMEM_TOTAL);

    dim3 grid(NN / TN, BATCH);   // (8,16) = 128 blocks
    actor_mma_kernel<<<grid, NTH, SMEM_TOTAL>>>(kv, pos, out);
}